// round 11
// baseline (speedup 1.0000x reference)
#include <cuda_runtime.h>
#include <cstdint>

// Problem shape (fixed by the dataset problem)
#define B_  32
#define T_  1600
#define C_  1024
#define L_  128

// Device scratch (allocation-free rule: __device__ globals).
// g_emOdd: per (b,t) row, 128 odd-state emission RATIOS r = p(label)/p(blank),
// one float4 per lane (lane l -> states 8l+1,8l+3,8l+5,8l+7).
// 64 pad rows so ring refill and L2 prefetch may run past the end harmlessly.
__device__ float g_emOdd[((size_t)B_ * T_ + 64) * 128];
__device__ float g_bll[B_ * T_];        // log-prob of blank per row (nats)
__device__ float g_lse[B_ * T_];        // per-(b,t) logsumexp (normalizer)
__device__ int   g_done[4][T_];         // per-(batch-group, t) completion flags

// ---------------------------------------------------------------------------
// Flag-zero kernel (runs before the fused kernel each call)
// ---------------------------------------------------------------------------
__global__ void ctc_zero()
{
    int i = blockIdx.x * blockDim.x + threadIdx.x;
    if (i < 4 * T_) ((int*)g_done)[i] = 0;
}

// acquire-poll on a completion flag
__device__ __forceinline__ void waitrow(int g, int t)
{
    const int* fp = &g_done[g][t];
    int f;
    asm volatile("ld.acquire.gpu.global.b32 %0, [%1];" : "=r"(f) : "l"(fp));
    while (f == 0) {
        asm volatile("ld.acquire.gpu.global.b32 %0, [%1];" : "=r"(f) : "l"(fp));
    }
}

// ---------------------------------------------------------------------------
// Fused kernel.
//  bid 0..31   : alpha recursion for batch b = bid (warp 0 only)
//  bid 32..6431: pass1, t-major — block i' = bid-32 covers rows
//                r = 8*i' + warp -> (t = r>>5, b = r&31): one t, batches
//                8*(i'&3)..+7. After its 8 rows are written: release-store
//                g_done[i'&3][i'>>2] = 1.
// ---------------------------------------------------------------------------
__global__ void __launch_bounds__(256) ctc_fused(
    const float* __restrict__ lp,       // [B,T,C]
    const int*   __restrict__ targets,  // [B,L]
    const int*   __restrict__ in_len,
    const int*   __restrict__ tgt_len,
    float*       __restrict__ out)
{
    // ======================= pass1 blocks =======================
    if (blockIdx.x >= 32) {
        int ip   = blockIdx.x - 32;
        int r    = 8 * ip + (threadIdx.x >> 5);   // row id 0..51199
        int lane = threadIdx.x & 31;
        int t = r >> 5;
        int b = r & 31;
        size_t rowb = (size_t)b * T_ + t;

        const float* row = lp + rowb * C_;
        const float4* row4 = (const float4*)row;

        float4 v[8];
        float m = -1e30f;
#pragma unroll
        for (int k = 0; k < 8; ++k) {
            v[k] = row4[lane + 32 * k];
            m = fmaxf(m, fmaxf(fmaxf(v[k].x, v[k].y), fmaxf(v[k].z, v[k].w)));
        }
#pragma unroll
        for (int o = 16; o; o >>= 1) m = fmaxf(m, __shfl_xor_sync(0xffffffffu, m, o));

        float s = 0.f;
#pragma unroll
        for (int k = 0; k < 8; ++k) {
            s += __expf(v[k].x - m) + __expf(v[k].y - m)
               + __expf(v[k].z - m) + __expf(v[k].w - m);
        }
#pragma unroll
        for (int o = 16; o; o >>= 1) s += __shfl_xor_sync(0xffffffffu, s, o);

        if (lane == 0) g_lse[rowb] = m + __logf(s);

        // 4 labels per lane -> odd states 8l+1..8l+7 ; ratios vs blank.
        const int4 tgv = *(const int4*)(targets + b * L_ + 4 * lane);
        float blv = row[0];
        float4 outv;
        outv.x = __expf(row[tgv.x] - blv);
        outv.y = __expf(row[tgv.y] - blv);
        outv.z = __expf(row[tgv.z] - blv);
        outv.w = __expf(row[tgv.w] - blv);
        *(float4*)(g_emOdd + (rowb << 7) + (lane << 2)) = outv;

        if (lane == 0) g_bll[rowb] = blv;

        __syncthreads();                      // all 8 rows of this block written
        if (threadIdx.x == 0) {
            int g  = ip & 3;
            int tt = ip >> 2;
            asm volatile("membar.gl;" ::: "memory");
            asm volatile("st.release.gpu.global.b32 [%0], %1;"
                         :: "l"(&g_done[g][tt]), "r"(1) : "memory");
        }
        return;
    }

    // ======================= alpha blocks =======================
    if (threadIdx.x >= 32) return;            // warp 0 only

    int b    = blockIdx.x;
    int lane = threadIdx.x;
    int g    = b >> 3;

    int Tin = in_len[b];
    int Sb  = 2 * tgt_len[b] + 1;

    const size_t rowb = (size_t)b * T_;

    // skip flags for own odd states (label index li = 4*lane + j) — input-only
    const int* tg = targets + b * L_;
    int li = 4 * lane;
    float sk1 = (lane > 0 && tg[li] != tg[li - 1]) ? 1.f : 0.f;
    float sk3 = (tg[li + 1] != tg[li])     ? 1.f : 0.f;
    float sk5 = (tg[li + 2] != tg[li + 1]) ? 1.f : 0.f;
    float sk7 = (tg[li + 3] != tg[li + 2]) ? 1.f : 0.f;

    const float4* emO = (const float4*)g_emOdd;    // 32 float4 per row
    const float* lseb = g_lse + rowb;
    const float* bllb = g_bll + rowb;

    // t = 0 init (needs row 0 published)
    waitrow(g, 0);
    float o0=0.f,o1=0.f,o2=0.f,o3=0.f,o4=0.f,o5=0.f,o6=0.f,o7=0.f,o8=0.f;
    float eb0_l0 = __expf(bllb[0]);
    if (lane == 0) {
        o0 = eb0_l0;
        o1 = g_emOdd[rowb << 7] * eb0_l0;
    }
    int   lsc = 0;
    float ff  = 0.f;

    int nst = Tin - 1;   // steps t = 1..Tin-1 (Tin >= 800)

// Renorm boundary (every 4 steps): anchor lane-pair max in [1,2) (biased 127,
// R8/R10-proven numerics — FROZEN). Left lane's new scale recomputed locally
// from absL/absLL so the two shfls are independent. Exact powers of 2.
#define BOUNDARY()                                                           \
    {                                                                        \
        float lm = fmaxf(fmaxf(fmaxf(o0,o1),fmaxf(o2,o3)),                   \
                         fmaxf(fmaxf(o4,o5),fmaxf(fmaxf(o6,o7),o8)));        \
        int elm   = __float_as_int(lm) >> 23;                                \
        int myabs = lsc + elm;                                               \
        int absL  = __shfl_up_sync(0xffffffffu, myabs, 1);                   \
        int absLL = __shfl_up_sync(0xffffffffu, myabs, 2);                   \
        if (lane < 1) absL  = myabs;                                         \
        if (lane < 2) absLL = -(1 << 29);                                    \
        int lscN  = ::max(myabs, absL)  - 127;                               \
        int lscNL = ::max(absL,  absLL) - 127;                               \
        int eo = ::min(::max(lsc - lscN + 127, 0), 254);                     \
        float sc = __int_as_float(eo << 23);                                 \
        int ef = ::min(::max(lscNL - lscN + 127, 0), 254);                   \
        ff = (lane == 0) ? 0.f : __int_as_float(ef << 23);                   \
        o0*=sc; o1*=sc; o2*=sc; o3*=sc; o4*=sc;                              \
        o5*=sc; o6*=sc; o7*=sc; o8*=sc;                                      \
        lsc = lscN;                                                          \
    }

// One time step: 17 fma-pipe ops + 1 shfl.
#define STEP(Ec)                                                             \
    {                                                                        \
        float h3 = __shfl_up_sync(0xffffffffu, o7, 1) * ff;                  \
        float n0 = o0 + h3;                                                  \
        float n1 = (Ec).x * fmaf(sk1, h3, o1 + o0);                          \
        float n2 = o2 + o1;                                                  \
        float n3 = (Ec).y * fmaf(sk3, o1, o3 + o2);                          \
        float n4 = o4 + o3;                                                  \
        float n5 = (Ec).z * fmaf(sk5, o3, o5 + o4);                          \
        float n6 = o6 + o5;                                                  \
        float n7 = (Ec).w * fmaf(sk7, o5, o7 + o6);                          \
        float n8 = o8 + o7;                                                  \
        o0=n0;o1=n1;o2=n2;o3=n3;o4=n4;o5=n5;o6=n6;o7=n7;o8=n8;               \
    }

    // emission ring, depth 16 (rows t = 1..16); poll each row's flag first
    float4 E[16];
#pragma unroll
    for (int i = 0; i < 16; ++i) {
        waitrow(g, 1 + i);
        E[i] = emO[(rowb + 1 + i) * 32 + lane];
    }

    const float4* pE = emO + (rowb + 17) * 32 + lane;   // refill base (row 1+k+16)

    int k = 0;
    while (k + 16 <= nst) {
#pragma unroll
        for (int q = 0; q < 4; ++q) {
            BOUNDARY();
#pragma unroll
            for (int j = 0; j < 4; ++j) {
                int u = 4 * q + j;
                int rr = k + u + 17;                        // row being refilled
                waitrow(g, rr < T_ ? rr : T_ - 1);
                float4 Ec = E[u];
                E[u] = pE[u * 32];                          // refill row 1+k+u+16
                asm volatile("prefetch.global.L2 [%0];"
                             :: "l"(pE + (u + 32) * 32));   // row 1+k+u+48 -> L2
                STEP(Ec);
            }
        }
        k  += 16;
        pE += 512;
    }

    // tail: <=4 steps per boundary, direct loads (rows already polled)
    while (k < nst) {
        BOUNDARY();
#pragma unroll 1
        for (int j = 0; j < 4 && k < nst; ++j, ++k) {
            float4 Ec = emO[(rowb + 1 + k) * 32 + lane];
            STEP(Ec);
        }
    }

    // deferred prologue reductions (all rows t < Tin published by now):
    // norm = sum lse; blsum = sum_{t>=1} lp_blank — same order as before.
    float nacc = 0.f, bacc = 0.f;
    for (int t = lane; t < Tin; t += 32) { nacc += lseb[t]; bacc += bllb[t]; }
#pragma unroll
    for (int o = 16; o; o >>= 1) {
        nacc += __shfl_xor_sync(0xffffffffu, nacc, o);
        bacc += __shfl_xor_sync(0xffffffffu, bacc, o);
    }
    float norm  = nacc;
    float blsum = bacc - bllb[0];   // exclude t = 0

    // final readout: combine states Sb-1, Sb-2 in log space (per-lane scales)
    __shared__ float fin[257];
    __shared__ int   flsc[32];
    fin[8*lane+0]=o0; fin[8*lane+1]=o1; fin[8*lane+2]=o2; fin[8*lane+3]=o3;
    fin[8*lane+4]=o4; fin[8*lane+5]=o5; fin[8*lane+6]=o6; fin[8*lane+7]=o7;
    if (lane == 31) fin[256] = o8;
    flsc[lane] = lsc;
    __syncwarp();

    if (lane == 0) {
        int sA = Sb - 1, sB = Sb - 2;
        int lA_ = sA >> 3; if (lA_ > 31) lA_ = 31;
        int lB_ = sB >> 3; if (lB_ > 31) lB_ = 31;
        float  va = fin[sA], vb = fin[sB];
        double lA = (va > 0.f) ? (log2((double)va) + (double)flsc[lA_]) : -1e300;
        double lB = (vb > 0.f) ? (log2((double)vb) + (double)flsc[lB_]) : -1e300;
        double hi = (lA > lB) ? lA : lB;
        double lo = (lA > lB) ? lB : lA;
        double l2sum = hi + log2(1.0 + exp2(lo - hi));
        double llh = 0.6931471805599453 * l2sum + (double)blsum;
        out[b] = (float)((double)norm - llh);
    }
#undef BOUNDARY
#undef STEP
}

// ---------------------------------------------------------------------------
extern "C" void kernel_launch(void* const* d_in, const int* in_sizes, int n_in,
                              void* d_out, int out_size)
{
    const float* lp      = (const float*)d_in[0];
    const int*   targets = (const int*)d_in[1];
    const int*   ilen    = (const int*)d_in[2];
    const int*   tlen    = (const int*)d_in[3];
    float*       out     = (float*)d_out;
    (void)in_sizes; (void)n_in; (void)out_size;

    ctc_zero<<<(4 * T_ + 255) / 256, 256>>>();
    // 32 alpha blocks + 6400 pass1 blocks (8 rows each), one fused kernel
    ctc_fused<<<32 + (B_ * T_) / 8, 256>>>(lp, targets, ilen, tlen, out);
}

// round 12
// speedup vs baseline: 4.3159x; 4.3159x over previous
#include <cuda_runtime.h>
#include <cstdint>

// Problem shape (fixed by the dataset problem)
#define B_  32
#define T_  1600
#define C_  1024
#define L_  128

// Device scratch (allocation-free rule: __device__ globals).
// g_emOdd: per (b,t) row, 128 odd-state emission RATIOS r = p(label)/p(blank),
// one float4 per lane (lane l -> states 8l+1,8l+3,8l+5,8l+7).
// 64 pad rows so ring refill and L2 prefetch may run past the end harmlessly.
__device__ float g_emOdd[((size_t)B_ * T_ + 64) * 128];
__device__ float g_bll[B_ * T_];        // log-prob of blank per row (nats)
__device__ float g_lse[B_ * T_];        // per-(b,t) logsumexp (normalizer)

// ---------------------------------------------------------------------------
// Pass 1: one warp per (b,t) row of log_probs.
// ---------------------------------------------------------------------------
__global__ void __launch_bounds__(256) ctc_pass1(
    const float* __restrict__ lp,       // [B,T,C]
    const int*   __restrict__ targets)  // [B,L]
{
    int warp = (blockIdx.x * blockDim.x + threadIdx.x) >> 5;
    int lane = threadIdx.x & 31;
    if (warp >= B_ * T_) return;

    int b = warp / T_;
    const float* row = lp + (size_t)warp * C_;
    const float4* row4 = (const float4*)row;

    float4 v[8];
    float m = -1e30f;
#pragma unroll
    for (int k = 0; k < 8; ++k) {
        v[k] = row4[lane + 32 * k];
        m = fmaxf(m, fmaxf(fmaxf(v[k].x, v[k].y), fmaxf(v[k].z, v[k].w)));
    }
#pragma unroll
    for (int o = 16; o; o >>= 1) m = fmaxf(m, __shfl_xor_sync(0xffffffffu, m, o));

    float s = 0.f;
#pragma unroll
    for (int k = 0; k < 8; ++k) {
        s += __expf(v[k].x - m) + __expf(v[k].y - m)
           + __expf(v[k].z - m) + __expf(v[k].w - m);
    }
#pragma unroll
    for (int o = 16; o; o >>= 1) s += __shfl_xor_sync(0xffffffffu, s, o);

    if (lane == 0) g_lse[warp] = m + __logf(s);

    // 4 labels per lane -> odd states 8l+1..8l+7 ; ratios vs blank.
    const int4 tgv = *(const int4*)(targets + b * L_ + 4 * lane);
    float blv = row[0];
    float4 outv;
    outv.x = __expf(row[tgv.x] - blv);
    outv.y = __expf(row[tgv.y] - blv);
    outv.z = __expf(row[tgv.z] - blv);
    outv.w = __expf(row[tgv.w] - blv);
    *(float4*)(g_emOdd + ((size_t)warp << 7) + (lane << 2)) = outv;

    if (lane == 0) g_bll[warp] = blv;
}

// ---------------------------------------------------------------------------
// Pass 2: blank-factored forward recursion, one WARP per batch.
// Even states: b' = b + b_left (FADD). Odd: b' = r*(b + b_left + sk*b_left2).
// Per-lane power-of-2 scale lsc, renorm every 4 steps, lane-pair max anchored
// to [1,2) (R8/R10-proven numerics — FROZEN).
// NEW: halo states h1,h2,h3 (= left lane's o5,o6,o7 scaled by ff) refreshed by
// independent shfls every 2 steps; h3 advanced locally in between (bit-exact
// vs per-step shfl because all scales are exact powers of 2). This takes the
// 26-cyc shfl off the per-step recurrence chain.
// Emission ring: 16 rows in registers + prefetch.global.L2 48 rows ahead.
// ---------------------------------------------------------------------------
__global__ void __launch_bounds__(32, 1) ctc_alpha(
    const int* __restrict__ targets,
    const int* __restrict__ in_len,
    const int* __restrict__ tgt_len,
    float*     __restrict__ out)
{
    int b    = blockIdx.x;
    int lane = threadIdx.x;

    int Tin = in_len[b];
    int Sb  = 2 * tgt_len[b] + 1;

    const size_t rowb = (size_t)b * T_;

    // prologue reductions: norm = sum lse; blsum = sum_{t>=1} lp_blank
    const float* lseb = g_lse + rowb;
    const float* bllb = g_bll + rowb;
    float nacc = 0.f, bacc = 0.f;
    for (int t = lane; t < Tin; t += 32) { nacc += lseb[t]; bacc += bllb[t]; }
#pragma unroll
    for (int o = 16; o; o >>= 1) {
        nacc += __shfl_xor_sync(0xffffffffu, nacc, o);
        bacc += __shfl_xor_sync(0xffffffffu, bacc, o);
    }
    float norm  = nacc;
    float blsum = bacc - bllb[0];   // exclude t = 0

    // skip flags: own odd states (li = 4*lane + j) + halo state 8l-1 (li = 4l-1)
    const int* tg = targets + b * L_;
    int li = 4 * lane;
    float sk1 = (lane > 0 && tg[li] != tg[li - 1]) ? 1.f : 0.f;
    float sk3 = (tg[li + 1] != tg[li])     ? 1.f : 0.f;
    float sk5 = (tg[li + 2] != tg[li + 1]) ? 1.f : 0.f;
    float sk7 = (tg[li + 3] != tg[li + 2]) ? 1.f : 0.f;
    float skh = (lane > 0 && tg[li - 1] != tg[li - 2]) ? 1.f : 0.f;

    const float4* emO = (const float4*)g_emOdd;    // 32 float4 per row

    // t = 0 init
    float o0=0.f,o1=0.f,o2=0.f,o3=0.f,o4=0.f,o5=0.f,o6=0.f,o7=0.f,o8=0.f;
    float h1=0.f,h2=0.f,h3=0.f;
    if (lane == 0) {
        float eb0 = __expf(bllb[0]);
        o0 = eb0;
        o1 = g_emOdd[rowb << 7] * eb0;
    }
    int   lsc = 0;
    float ff  = 0.f;

    int nst = Tin - 1;   // steps t = 1..Tin-1 (Tin >= 800)

// Renorm boundary (every 4 steps) — FROZEN R10 numerics.
#define BOUNDARY()                                                           \
    {                                                                        \
        float lm = fmaxf(fmaxf(fmaxf(o0,o1),fmaxf(o2,o3)),                   \
                         fmaxf(fmaxf(o4,o5),fmaxf(fmaxf(o6,o7),o8)));        \
        int elm   = __float_as_int(lm) >> 23;                                \
        int myabs = lsc + elm;                                               \
        int absL  = __shfl_up_sync(0xffffffffu, myabs, 1);                   \
        int absLL = __shfl_up_sync(0xffffffffu, myabs, 2);                   \
        if (lane < 1) absL  = myabs;                                         \
        if (lane < 2) absLL = -(1 << 29);                                    \
        int lscN  = ::max(myabs, absL)  - 127;                               \
        int lscNL = ::max(absL,  absLL) - 127;                               \
        int eo = ::min(::max(lsc - lscN + 127, 0), 254);                     \
        float sc = __int_as_float(eo << 23);                                 \
        int ef = ::min(::max(lscNL - lscN + 127, 0), 254);                   \
        ff = (lane == 0) ? 0.f : __int_as_float(ef << 23);                   \
        o0*=sc; o1*=sc; o2*=sc; o3*=sc; o4*=sc;                              \
        o5*=sc; o6*=sc; o7*=sc; o8*=sc;                                      \
        lsc = lscN;                                                          \
    }

// Halo refresh (every 2 steps): 3 independent shfls, period-constant ff.
#define REFRESH()                                                            \
    {                                                                        \
        float v5 = __shfl_up_sync(0xffffffffu, o5, 1);                       \
        float v6 = __shfl_up_sync(0xffffffffu, o6, 1);                       \
        float v7 = __shfl_up_sync(0xffffffffu, o7, 1);                       \
        h1 = v5 * ff; h2 = v6 * ff; h3 = v7 * ff;                            \
    }

// Step with local halo advance (first step of each pair, and tail steps).
// ehw = left lane's E.w (ring data — off the recurrence chain).
#define STEP_A(Ec)                                                           \
    {                                                                        \
        float ehw = __shfl_up_sync(0xffffffffu, (Ec).w, 1);                  \
        float nh3 = ehw * fmaf(skh, h1, h3 + h2);                            \
        float n0 = o0 + h3;                                                  \
        float n1 = (Ec).x * fmaf(sk1, h3, o1 + o0);                          \
        float n2 = o2 + o1;                                                  \
        float n3 = (Ec).y * fmaf(sk3, o1, o3 + o2);                          \
        float n4 = o4 + o3;                                                  \
        float n5 = (Ec).z * fmaf(sk5, o3, o5 + o4);                          \
        float n6 = o6 + o5;                                                  \
        float n7 = (Ec).w * fmaf(sk7, o5, o7 + o6);                          \
        float n8 = o8 + o7;                                                  \
        o0=n0;o1=n1;o2=n2;o3=n3;o4=n4;o5=n5;o6=n6;o7=n7;o8=n8;               \
        h3 = nh3;                                                            \
    }

// Second step of a pair: pure local math, no shfl at all.
#define STEP_B(Ec)                                                           \
    {                                                                        \
        float n0 = o0 + h3;                                                  \
        float n1 = (Ec).x * fmaf(sk1, h3, o1 + o0);                          \
        float n2 = o2 + o1;                                                  \
        float n3 = (Ec).y * fmaf(sk3, o1, o3 + o2);                          \
        float n4 = o4 + o3;                                                  \
        float n5 = (Ec).z * fmaf(sk5, o3, o5 + o4);                          \
        float n6 = o6 + o5;                                                  \
        float n7 = (Ec).w * fmaf(sk7, o5, o7 + o6);                          \
        float n8 = o8 + o7;                                                  \
        o0=n0;o1=n1;o2=n2;o3=n3;o4=n4;o5=n5;o6=n6;o7=n7;o8=n8;               \
    }

    // emission ring, depth 16 (rows t = 1..16); pad rows make OOB reads safe
    float4 E[16];
#pragma unroll
    for (int i = 0; i < 16; ++i) E[i] = emO[(rowb + 1 + i) * 32 + lane];

    const float4* pE = emO + (rowb + 17) * 32 + lane;   // refill base (row 1+k+16)

    int k = 0;
    while (k + 16 <= nst) {
#pragma unroll
        for (int q = 0; q < 4; ++q) {
            BOUNDARY();
            REFRESH();
            {
                int u = 4 * q;
                float4 Ec = E[u];
                E[u] = pE[u * 32];
                asm volatile("prefetch.global.L2 [%0];"
                             :: "l"(pE + (u + 32) * 32));
                STEP_A(Ec);
            }
            {
                int u = 4 * q + 1;
                float4 Ec = E[u];
                E[u] = pE[u * 32];
                asm volatile("prefetch.global.L2 [%0];"
                             :: "l"(pE + (u + 32) * 32));
                STEP_B(Ec);
            }
            REFRESH();
            {
                int u = 4 * q + 2;
                float4 Ec = E[u];
                E[u] = pE[u * 32];
                asm volatile("prefetch.global.L2 [%0];"
                             :: "l"(pE + (u + 32) * 32));
                STEP_A(Ec);
            }
            {
                int u = 4 * q + 3;
                float4 Ec = E[u];
                E[u] = pE[u * 32];
                asm volatile("prefetch.global.L2 [%0];"
                             :: "l"(pE + (u + 32) * 32));
                STEP_B(Ec);
            }
        }
        k  += 16;
        pE += 512;
    }

    // tail: <=4 steps per boundary; refresh before every step (cheap, exact)
    while (k < nst) {
        BOUNDARY();
#pragma unroll 1
        for (int j = 0; j < 4 && k < nst; ++j, ++k) {
            REFRESH();
            float4 Ec = emO[(rowb + 1 + k) * 32 + lane];
            STEP_A(Ec);
        }
    }

    // final readout: combine states Sb-1, Sb-2 in log space (per-lane scales)
    __shared__ float fin[257];
    __shared__ int   flsc[32];
    fin[8*lane+0]=o0; fin[8*lane+1]=o1; fin[8*lane+2]=o2; fin[8*lane+3]=o3;
    fin[8*lane+4]=o4; fin[8*lane+5]=o5; fin[8*lane+6]=o6; fin[8*lane+7]=o7;
    if (lane == 31) fin[256] = o8;
    flsc[lane] = lsc;
    __syncwarp();

    if (lane == 0) {
        int sA = Sb - 1, sB = Sb - 2;
        int lA_ = sA >> 3; if (lA_ > 31) lA_ = 31;
        int lB_ = sB >> 3; if (lB_ > 31) lB_ = 31;
        float  va = fin[sA], vb = fin[sB];
        double lA = (va > 0.f) ? (log2((double)va) + (double)flsc[lA_]) : -1e300;
        double lB = (vb > 0.f) ? (log2((double)vb) + (double)flsc[lB_]) : -1e300;
        double hi = (lA > lB) ? lA : lB;
        double lo = (lA > lB) ? lB : lA;
        double l2sum = hi + log2(1.0 + exp2(lo - hi));
        double llh = 0.6931471805599453 * l2sum + (double)blsum;
        out[b] = (float)((double)norm - llh);
    }
#undef BOUNDARY
#undef REFRESH
#undef STEP_A
#undef STEP_B
}

// ---------------------------------------------------------------------------
extern "C" void kernel_launch(void* const* d_in, const int* in_sizes, int n_in,
                              void* d_out, int out_size)
{
    const float* lp      = (const float*)d_in[0];
    const int*   targets = (const int*)d_in[1];
    const int*   ilen    = (const int*)d_in[2];
    const int*   tlen    = (const int*)d_in[3];
    float*       out     = (float*)d_out;
    (void)in_sizes; (void)n_in; (void)out_size;

    ctc_pass1<<<(B_ * T_) / 8, 256>>>(lp, targets);
    ctc_alpha<<<B_, 32>>>(targets, ilen, tlen, out);
}

// round 14
// speedup vs baseline: 4.6224x; 1.0710x over previous
#include <cuda_runtime.h>
#include <cstdint>

// Problem shape (fixed by the dataset problem)
#define B_  32
#define T_  1600
#define C_  1024
#define L_  128

// Device scratch (allocation-free rule: __device__ globals).
// g_emOdd: per (b,t) row, 128 odd-state emission RATIOS r = p(label)/p(blank),
// one float4 per lane (lane l -> states 8l+1,8l+3,8l+5,8l+7).
// 64 pad rows so ring refill and L2 prefetch may run past the end harmlessly.
__device__ float g_emOdd[((size_t)B_ * T_ + 64) * 128];
__device__ float g_bll[B_ * T_];        // log-prob of blank per row (nats)

// ---------------------------------------------------------------------------
// Pass 1: one warp per (b,t) row. PURE GATHER — the reference normalizer
// logsumexp(log_softmax) == 0 analytically, so no full-row reduction needed.
// Each lane gathers its 4 label log-probs + the shared blank, writes ratios.
// ---------------------------------------------------------------------------
__global__ void __launch_bounds__(256) ctc_pass1(
    const float* __restrict__ lp,       // [B,T,C]
    const int*   __restrict__ targets)  // [B,L]
{
    int warp = (blockIdx.x * blockDim.x + threadIdx.x) >> 5;
    int lane = threadIdx.x & 31;
    if (warp >= B_ * T_) return;

    int b = warp / T_;
    const float* row = lp + (size_t)warp * C_;

    // 4 labels per lane -> odd states 8l+1..8l+7 ; ratios vs blank.
    const int4 tgv = *(const int4*)(targets + b * L_ + 4 * lane);
    float blv = row[0];                  // warp-broadcast load
    float e0 = row[tgv.x];
    float e1 = row[tgv.y];
    float e2 = row[tgv.z];
    float e3 = row[tgv.w];

    float4 outv;
    outv.x = __expf(e0 - blv);
    outv.y = __expf(e1 - blv);
    outv.z = __expf(e2 - blv);
    outv.w = __expf(e3 - blv);
    *(float4*)(g_emOdd + ((size_t)warp << 7) + (lane << 2)) = outv;

    if (lane == 0) g_bll[warp] = blv;
}

// ---------------------------------------------------------------------------
// Pass 2: blank-factored forward recursion, one WARP per batch.
// EXACT R10 kernel (proven at 73.6us / rel_err 1.68e-6), minus the dead
// g_lse normalizer reduction. Numerics FROZEN: per-lane power-of-2 scale,
// renorm every 4 steps, lane-pair max anchored to [1,2); per-step cross-lane
// term h3 = shfl_up(o7) * ff with period-constant ff (0 on lane 0).
// Emission ring: 16 rows in registers + prefetch.global.L2 48 rows ahead.
// ---------------------------------------------------------------------------
__global__ void __launch_bounds__(32, 1) ctc_alpha(
    const int* __restrict__ targets,
    const int* __restrict__ in_len,
    const int* __restrict__ tgt_len,
    float*     __restrict__ out)
{
    int b    = blockIdx.x;
    int lane = threadIdx.x;

    int Tin = in_len[b];
    int Sb  = 2 * tgt_len[b] + 1;

    const size_t rowb = (size_t)b * T_;

    // prologue reduction: blsum = sum_{t in [1,Tin)} lp_blank
    const float* bllb = g_bll + rowb;
    float bacc = 0.f;
    for (int t = lane; t < Tin; t += 32) bacc += bllb[t];
#pragma unroll
    for (int o = 16; o; o >>= 1) bacc += __shfl_xor_sync(0xffffffffu, bacc, o);
    float blsum = bacc - bllb[0];   // exclude t = 0

    // skip flags for own odd states (label index li = 4*lane + j)
    const int* tg = targets + b * L_;
    int li = 4 * lane;
    float sk1 = (lane > 0 && tg[li] != tg[li - 1]) ? 1.f : 0.f;
    float sk3 = (tg[li + 1] != tg[li])     ? 1.f : 0.f;
    float sk5 = (tg[li + 2] != tg[li + 1]) ? 1.f : 0.f;
    float sk7 = (tg[li + 3] != tg[li + 2]) ? 1.f : 0.f;

    const float4* emO = (const float4*)g_emOdd;    // 32 float4 per row

    // t = 0 init
    float o0=0.f,o1=0.f,o2=0.f,o3=0.f,o4=0.f,o5=0.f,o6=0.f,o7=0.f,o8=0.f;
    if (lane == 0) {
        float eb0 = __expf(bllb[0]);
        o0 = eb0;
        o1 = g_emOdd[rowb << 7] * eb0;
    }
    int   lsc = 0;
    float ff  = 0.f;

    int nst = Tin - 1;   // steps t = 1..Tin-1 (Tin >= 800)

// Renorm boundary (every 4 steps): anchor lane-pair max in [1,2) (biased 127,
// R8/R10-proven numerics — FROZEN, byte-for-byte). Left lane's new scale
// recomputed locally from absL/absLL so the two shfls are independent.
#define BOUNDARY()                                                           \
    {                                                                        \
        float lm = fmaxf(fmaxf(fmaxf(o0,o1),fmaxf(o2,o3)),                   \
                         fmaxf(fmaxf(o4,o5),fmaxf(fmaxf(o6,o7),o8)));        \
        int elm   = __float_as_int(lm) >> 23;                                \
        int myabs = lsc + elm;                                               \
        int absL  = __shfl_up_sync(0xffffffffu, myabs, 1);                   \
        int absLL = __shfl_up_sync(0xffffffffu, myabs, 2);                   \
        if (lane < 1) absL  = myabs;                                         \
        if (lane < 2) absLL = -(1 << 29);                                    \
        int lscN  = ::max(myabs, absL)  - 127;                               \
        int lscNL = ::max(absL,  absLL) - 127;                               \
        int eo = ::min(::max(lsc - lscN + 127, 0), 254);                     \
        float sc = __int_as_float(eo << 23);                                 \
        int ef = ::min(::max(lscNL - lscN + 127, 0), 254);                   \
        ff = (lane == 0) ? 0.f : __int_as_float(ef << 23);                   \
        o0*=sc; o1*=sc; o2*=sc; o3*=sc; o4*=sc;                              \
        o5*=sc; o6*=sc; o7*=sc; o8*=sc;                                      \
        lsc = lscN;                                                          \
    }

// One time step: 17 fma-pipe ops + 1 shfl.
#define STEP(Ec)                                                             \
    {                                                                        \
        float h3 = __shfl_up_sync(0xffffffffu, o7, 1) * ff;                  \
        float n0 = o0 + h3;                                                  \
        float n1 = (Ec).x * fmaf(sk1, h3, o1 + o0);                          \
        float n2 = o2 + o1;                                                  \
        float n3 = (Ec).y * fmaf(sk3, o1, o3 + o2);                          \
        float n4 = o4 + o3;                                                  \
        float n5 = (Ec).z * fmaf(sk5, o3, o5 + o4);                          \
        float n6 = o6 + o5;                                                  \
        float n7 = (Ec).w * fmaf(sk7, o5, o7 + o6);                          \
        float n8 = o8 + o7;                                                  \
        o0=n0;o1=n1;o2=n2;o3=n3;o4=n4;o5=n5;o6=n6;o7=n7;o8=n8;               \
    }

    // emission ring, depth 16 (rows t = 1..16); pad rows make OOB reads safe
    float4 E[16];
#pragma unroll
    for (int i = 0; i < 16; ++i) E[i] = emO[(rowb + 1 + i) * 32 + lane];

    const float4* pE = emO + (rowb + 17) * 32 + lane;   // refill base (row 1+k+16)

    int k = 0;
    while (k + 16 <= nst) {
#pragma unroll
        for (int q = 0; q < 4; ++q) {
            BOUNDARY();
#pragma unroll
            for (int j = 0; j < 4; ++j) {
                int u = 4 * q + j;
                float4 Ec = E[u];
                E[u] = pE[u * 32];                          // refill row 1+k+u+16
                asm volatile("prefetch.global.L2 [%0];"
                             :: "l"(pE + (u + 32) * 32));   // row 1+k+u+48 -> L2
                STEP(Ec);
            }
        }
        k  += 16;
        pE += 512;
    }

    // tail: <=4 steps per boundary, direct L2-hot loads
    while (k < nst) {
        BOUNDARY();
#pragma unroll 1
        for (int j = 0; j < 4 && k < nst; ++j, ++k) {
            float4 Ec = emO[(rowb + 1 + k) * 32 + lane];
            STEP(Ec);
        }
    }

    // final readout: combine states Sb-1, Sb-2 in log space (per-lane scales)
    __shared__ float fin[257];
    __shared__ int   flsc[32];
    fin[8*lane+0]=o0; fin[8*lane+1]=o1; fin[8*lane+2]=o2; fin[8*lane+3]=o3;
    fin[8*lane+4]=o4; fin[8*lane+5]=o5; fin[8*lane+6]=o6; fin[8*lane+7]=o7;
    if (lane == 31) fin[256] = o8;
    flsc[lane] = lsc;
    __syncwarp();

    if (lane == 0) {
        int sA = Sb - 1, sB = Sb - 2;
        int lA_ = sA >> 3; if (lA_ > 31) lA_ = 31;
        int lB_ = sB >> 3; if (lB_ > 31) lB_ = 31;
        float  va = fin[sA], vb = fin[sB];
        double lA = (va > 0.f) ? (log2((double)va) + (double)flsc[lA_]) : -1e300;
        double lB = (vb > 0.f) ? (log2((double)vb) + (double)flsc[lB_]) : -1e300;
        double hi = (lA > lB) ? lA : lB;
        double lo = (lA > lB) ? lB : lA;
        double l2sum = hi + log2(1.0 + exp2(lo - hi));
        double llh = 0.6931471805599453 * l2sum + (double)blsum;
        out[b] = (float)(-llh);     // normalizer of log_softmax rows == 0
    }
#undef BOUNDARY
#undef STEP
}

// ---------------------------------------------------------------------------
extern "C" void kernel_launch(void* const* d_in, const int* in_sizes, int n_in,
                              void* d_out, int out_size)
{
    const float* lp      = (const float*)d_in[0];
    const int*   targets = (const int*)d_in[1];
    const int*   ilen    = (const int*)d_in[2];
    const int*   tlen    = (const int*)d_in[3];
    float*       out     = (float*)d_out;
    (void)in_sizes; (void)n_in; (void)out_size;

    ctc_pass1<<<(B_ * T_) / 8, 256>>>(lp, targets);
    ctc_alpha<<<B_, 32>>>(targets, ilen, tlen, out);
}